// round 14
// baseline (speedup 1.0000x reference)
#include <cuda_runtime.h>
#include <cuda_bf16.h>
#include <stdint.h>
#include <math.h>

#define BATCH 4
#define SEQ   2048
#define HDIM  1024
#define EDIM  1024
#define MTOT  (BATCH * SEQ)          // 8192

typedef __nv_bfloat16 bf16;

// ---------------------------------------------------------------------------
// Scratch (device globals)
// ---------------------------------------------------------------------------
__device__ bf16  g_xh[(size_t)MTOT * HDIM],  g_xl[(size_t)MTOT * HDIM];
__device__ bf16  g_wh[(size_t)3 * EDIM * HDIM], g_wl[(size_t)3 * EDIM * HDIM];
__device__ bf16  g_qh[(size_t)MTOT * EDIM],  g_ql[(size_t)MTOT * EDIM];
__device__ bf16  g_kh[(size_t)MTOT * EDIM],  g_kl[(size_t)MTOT * EDIM];
__device__ bf16  g_vth[(size_t)EDIM * MTOT], g_vtl[(size_t)EDIM * MTOT];
__device__ float g_p [(size_t)BATCH * SEQ * SEQ];
__device__ bf16  g_ph[(size_t)BATCH * SEQ * SEQ], g_pl[(size_t)BATCH * SEQ * SEQ];

// ---------------------------------------------------------------------------
// Geometry: CTA 128x128, K-chunk = 32 bf16 = 64B rows, XOR swizzle
// seg' = seg ^ ((row>>1)&3). 256 threads = 8 warps (2 wm x 4 wn),
// warp tile 64x32. 2 stages x 32KB = 64KB smem -> 2 CTAs/SM.
// ---------------------------------------------------------------------------
#define TILE_B   (128 * 64)            // 8192 B per 128x32 bf16 tile
#define STAGE_B  (4 * TILE_B)          // Ah, Al, Bh, Bl = 32768 B
#define SMEM_BYTES (2 * STAGE_B)       // 65536 B double buffered
#define NTHREADS 256

__device__ __forceinline__ uint32_t smem_u32(const void* p) {
    uint32_t a;
    asm("{ .reg .u64 t; cvta.to.shared.u64 t, %1; cvt.u32.u64 %0, t; }"
        : "=r"(a) : "l"(p));
    return a;
}
__device__ __forceinline__ void cp_async16(uint32_t dst, const void* src) {
    asm volatile("cp.async.cg.shared.global [%0], [%1], 16;"
                 :: "r"(dst), "l"(src));
}
__device__ __forceinline__ void cp_commit() {
    asm volatile("cp.async.commit_group;" ::: "memory");
}
template<int N> __device__ __forceinline__ void cp_wait() {
    asm volatile("cp.async.wait_group %0;" :: "n"(N) : "memory");
}
__device__ __forceinline__ void ldsm4(uint32_t* r, uint32_t addr) {
    asm volatile("ldmatrix.sync.aligned.m8n8.x4.shared.b16 {%0,%1,%2,%3}, [%4];"
                 : "=r"(r[0]), "=r"(r[1]), "=r"(r[2]), "=r"(r[3]) : "r"(addr));
}
__device__ __forceinline__ void mma16816(float* c, const uint32_t* a,
                                         uint32_t b0, uint32_t b1) {
    asm volatile(
        "mma.sync.aligned.m16n8k16.row.col.f32.bf16.bf16.f32 "
        "{%0,%1,%2,%3}, {%4,%5,%6,%7}, {%8,%9}, {%0,%1,%2,%3};"
        : "+f"(c[0]), "+f"(c[1]), "+f"(c[2]), "+f"(c[3])
        : "r"(a[0]), "r"(a[1]), "r"(a[2]), "r"(a[3]), "r"(b0), "r"(b1));
}
__device__ __forceinline__ void split2(float x, float y, uint32_t& h, uint32_t& l) {
    __nv_bfloat162 hh = __floats2bfloat162_rn(x, y);
    float rx = x - __low2float(hh);
    float ry = y - __high2float(hh);
    __nv_bfloat162 ll = __floats2bfloat162_rn(rx, ry);
    h = *(uint32_t*)&hh; l = *(uint32_t*)&ll;
}

// ---------------------------------------------------------------------------
// Issue one K-chunk (4 tiles of 128 rows x 64B) via cp.async, swizzled.
// 256 threads x 2 segs per tile x 4 tiles = 8 cp.async16 per thread.
// ---------------------------------------------------------------------------
__device__ __forceinline__ void stage_issue(
    const bf16* __restrict__ Ah, const bf16* __restrict__ Al, size_t lda,
    const bf16* __restrict__ Bh, const bf16* __restrict__ Bl, size_t ldb,
    int m0, int n0, int kt, uint32_t st, int tid)
{
    #pragma unroll
    for (int t = 0; t < 4; t++) {
        const bf16* base = (t == 0) ? Ah : (t == 1) ? Al : (t == 2) ? Bh : Bl;
        const size_t ld  = (t < 2) ? lda : ldb;
        const int    r0  = (t < 2) ? m0 : n0;
        #pragma unroll
        for (int jj = 0; jj < 2; jj++) {
            int idx = tid * 2 + jj;          // 0..511
            int r   = idx >> 2;              // 0..127
            int j   = idx & 3;               // 16B segment 0..3
            const bf16* gp = base + (size_t)(r0 + r) * ld + kt + j * 8;
            uint32_t dst = st + t * TILE_B + r * 64 + ((j ^ ((r >> 1) & 3)) << 4);
            cp_async16(dst, gp);
        }
    }
}

// ---------------------------------------------------------------------------
// 128x128 GEMM: C[m,n] = scale * sum_k A[m,k]*B[n,k] (+bias), bf16 split.
// 8 warps, warp tile 64x32. cp.async 2-stage ring (K-chunk 32), one barrier
// per chunk, swizzled smem, 2 CTAs/SM.
// ---------------------------------------------------------------------------
__device__ void gemm_mma(
    const bf16* __restrict__ Ah, const bf16* __restrict__ Al, size_t lda,
    const bf16* __restrict__ Bh, const bf16* __restrict__ Bl, size_t ldb,
    float* __restrict__ C, bf16* __restrict__ Ch, bf16* __restrict__ Cl,
    size_t ldc, const float* __restrict__ bias, int bias_mode, float scale,
    int m0, int n0, int nchunks)
{
    extern __shared__ __align__(128) char smem[];
    const uint32_t sbase = smem_u32(smem);
    const int tid  = threadIdx.x;
    const int lane = tid & 31;
    const int wid  = tid >> 5;       // 0..7
    const int wm   = wid >> 2;       // 0..1  (64-row slice)
    const int wn   = wid & 3;        // 0..3  (32-col slice)

    float acc[4][4][4];
    #pragma unroll
    for (int i = 0; i < 4; i++)
        #pragma unroll
        for (int j = 0; j < 4; j++)
            #pragma unroll
            for (int q = 0; q < 4; q++) acc[i][j][q] = 0.f;

    // fragment row bases (bytes) and lane-constant swizzle keys
    const uint32_t a_r  = (uint32_t)(wm * 64 + (lane & 15));
    const uint32_t b_r  = (uint32_t)(wn * 32 + (lane & 7) + ((lane >> 4) << 3));
    const uint32_t a_row = a_r * 64;
    const uint32_t b_row = b_r * 64;
    const uint32_t alx  = (a_r >> 1) & 3;
    const uint32_t blx  = (b_r >> 1) & 3;
    const uint32_t a_sg = (uint32_t)(lane >> 4);         // 0/1
    const uint32_t b_sg = (uint32_t)((lane >> 3) & 1);   // 0/1

    // prologue: chunk 0 -> buffer 0
    stage_issue(Ah, Al, lda, Bh, Bl, ldb, m0, n0, 0, sbase, tid);
    cp_commit();

    for (int c = 0; c < nchunks; ++c) {
        cp_wait<0>();
        __syncthreads();                 // chunk c visible; WAR for other buffer

        if (c + 1 < nchunks) {
            stage_issue(Ah, Al, lda, Bh, Bl, ldb, m0, n0, (c + 1) * 32,
                        sbase + ((c + 1) & 1) * STAGE_B, tid);
            cp_commit();
        }

        const uint32_t hiA = sbase + (c & 1) * STAGE_B;
        const uint32_t loA = hiA + TILE_B;
        const uint32_t hiB = hiA + 2 * TILE_B;
        const uint32_t loB = hiA + 3 * TILE_B;

        #pragma unroll
        for (int s = 0; s < 2; s++) {    // 2 k16-steps per 32-wide chunk
            const uint32_t aw = (((uint32_t)(2 * s) + a_sg) ^ alx) << 4;
            const uint32_t bw = (((uint32_t)(2 * s) + b_sg) ^ blx) << 4;
            uint32_t ah[4][4], al[4][4], bh[2][4], bl[2][4];

            // pass 1: hi*hi
            #pragma unroll
            for (int mt = 0; mt < 4; mt++)
                ldsm4(ah[mt], hiA + a_row + mt * 16 * 64 + aw);
            #pragma unroll
            for (int p = 0; p < 2; p++)
                ldsm4(bh[p], hiB + b_row + p * 16 * 64 + bw);
            #pragma unroll
            for (int mt = 0; mt < 4; mt++)
                #pragma unroll
                for (int p = 0; p < 2; p++) {
                    mma16816(acc[mt][2 * p],     ah[mt], bh[p][0], bh[p][1]);
                    mma16816(acc[mt][2 * p + 1], ah[mt], bh[p][2], bh[p][3]);
                }
            // pass 2: lo*hi
            #pragma unroll
            for (int mt = 0; mt < 4; mt++)
                ldsm4(al[mt], loA + a_row + mt * 16 * 64 + aw);
            #pragma unroll
            for (int mt = 0; mt < 4; mt++)
                #pragma unroll
                for (int p = 0; p < 2; p++) {
                    mma16816(acc[mt][2 * p],     al[mt], bh[p][0], bh[p][1]);
                    mma16816(acc[mt][2 * p + 1], al[mt], bh[p][2], bh[p][3]);
                }
            // pass 3: hi*lo
            #pragma unroll
            for (int p = 0; p < 2; p++)
                ldsm4(bl[p], loB + b_row + p * 16 * 64 + bw);
            #pragma unroll
            for (int mt = 0; mt < 4; mt++)
                #pragma unroll
                for (int p = 0; p < 2; p++) {
                    mma16816(acc[mt][2 * p],     ah[mt], bl[p][0], bl[p][1]);
                    mma16816(acc[mt][2 * p + 1], ah[mt], bl[p][2], bl[p][3]);
                }
        }
        // no bottom barrier: next write to this buffer only after the top
        // barrier of chunk c+1.
    }

    // epilogue: warp tile 64x32
    const int g   = lane >> 2;
    const int tig = lane & 3;
    #pragma unroll
    for (int mt = 0; mt < 4; mt++) {
        const int r0 = m0 + wm * 64 + mt * 16 + g;
        #pragma unroll
        for (int nt = 0; nt < 4; nt++) {
            const int col = n0 + wn * 32 + nt * 8 + tig * 2;
            float b0 = 0.f, b1 = 0.f;
            if (bias_mode == 1) { b0 = bias[col]; b1 = bias[col + 1]; }
            float v00 = acc[mt][nt][0] * scale + b0;
            float v01 = acc[mt][nt][1] * scale + b1;
            float v10 = acc[mt][nt][2] * scale + b0;
            float v11 = acc[mt][nt][3] * scale + b1;
            if (bias_mode == 2) {
                float rb0 = bias[r0], rb1 = bias[r0 + 8];
                v00 += rb0; v01 += rb0; v10 += rb1; v11 += rb1;
            }
            if (C) {
                *(float2*)(C + (size_t)r0 * ldc + col)       = make_float2(v00, v01);
                *(float2*)(C + (size_t)(r0 + 8) * ldc + col) = make_float2(v10, v11);
            } else {
                uint32_t h0, l0, h1, l1;
                split2(v00, v01, h0, l0);
                split2(v10, v11, h1, l1);
                *(uint32_t*)(Ch + (size_t)r0 * ldc + col)       = h0;
                *(uint32_t*)(Cl + (size_t)r0 * ldc + col)       = l0;
                *(uint32_t*)(Ch + (size_t)(r0 + 8) * ldc + col) = h1;
                *(uint32_t*)(Cl + (size_t)(r0 + 8) * ldc + col) = l1;
            }
        }
    }
}

// ---------------------------------------------------------------------------
// Prep: split xs and the 3 weight matrices into bf16 hi/lo.
// ---------------------------------------------------------------------------
__device__ __forceinline__ void cvt_arr(const float* __restrict__ in,
                                        bf16* __restrict__ hi,
                                        bf16* __restrict__ lo, size_t n4)
{
    const size_t t0 = blockIdx.x * blockDim.x + threadIdx.x;
    const size_t stride = (size_t)gridDim.x * blockDim.x;
    for (size_t i = t0; i < n4; i += stride) {
        float4 v = ((const float4*)in)[i];
        uint32_t h0, l0, h1, l1;
        split2(v.x, v.y, h0, l0);
        split2(v.z, v.w, h1, l1);
        ((uint2*)hi)[i] = make_uint2(h0, h1);
        ((uint2*)lo)[i] = make_uint2(l0, l1);
    }
}

__global__ __launch_bounds__(256) void prep_kernel(
    const float* __restrict__ xs, const float* __restrict__ wq,
    const float* __restrict__ wk, const float* __restrict__ wv)
{
    const size_t WN = (size_t)EDIM * HDIM;
    if      (blockIdx.y == 0) cvt_arr(xs, g_xh, g_xl, (size_t)MTOT * HDIM / 4);
    else if (blockIdx.y == 1) cvt_arr(wq, g_wh,          g_wl,          WN / 4);
    else if (blockIdx.y == 2) cvt_arr(wk, g_wh + WN,     g_wl + WN,     WN / 4);
    else                      cvt_arr(wv, g_wh + 2 * WN, g_wl + 2 * WN, WN / 4);
}

// ---------------------------------------------------------------------------
// GEMM wrappers (K-chunk = 32)
// ---------------------------------------------------------------------------
__global__ __launch_bounds__(NTHREADS, 2)
void proj_qk_kernel(const float* __restrict__ bq, const float* __restrict__ bk)
{
    const size_t WN = (size_t)EDIM * HDIM;
    const int z = blockIdx.z;
    gemm_mma(g_xh, g_xl, HDIM,
             g_wh + z * WN, g_wl + z * WN, HDIM,
             nullptr, z ? g_kh : g_qh, z ? g_kl : g_ql, EDIM,
             z ? bk : bq, 1, 1.0f,
             blockIdx.y * 128, blockIdx.x * 128, HDIM / 32);
}

__global__ __launch_bounds__(NTHREADS, 2)
void proj_vt_kernel(const float* __restrict__ bv)
{
    const size_t WN = (size_t)EDIM * HDIM;
    gemm_mma(g_wh + 2 * WN, g_wl + 2 * WN, HDIM,
             g_xh, g_xl, HDIM,
             nullptr, g_vth, g_vtl, MTOT,
             bv, 2, 1.0f,
             blockIdx.y * 128, blockIdx.x * 128, HDIM / 32);
}

__global__ __launch_bounds__(NTHREADS, 2)
void qkt_kernel()
{
    if (blockIdx.x > blockIdx.y) return;       // above diagonal: never read
    const int b = blockIdx.z;
    gemm_mma(g_qh + (size_t)b * SEQ * EDIM, g_ql + (size_t)b * SEQ * EDIM, EDIM,
             g_kh + (size_t)b * SEQ * EDIM, g_kl + (size_t)b * SEQ * EDIM, EDIM,
             g_p + (size_t)b * SEQ * SEQ, nullptr, nullptr, SEQ,
             nullptr, 0, 0.03125f,
             blockIdx.y * 128, blockIdx.x * 128, EDIM / 32);
}

__global__ __launch_bounds__(NTHREADS, 2)
void pv_kernel(float* __restrict__ out)
{
    const int b = blockIdx.z;
    const int nchunks = (blockIdx.y + 1) * 4;   // K bound = (y+1)*128
    gemm_mma(g_ph + (size_t)b * SEQ * SEQ, g_pl + (size_t)b * SEQ * SEQ, SEQ,
             g_vth + (size_t)b * SEQ, g_vtl + (size_t)b * SEQ, MTOT,
             out + (size_t)b * SEQ * EDIM, nullptr, nullptr, EDIM,
             nullptr, 0, 1.0f,
             blockIdx.y * 128, blockIdx.x * 128, nchunks);
}

// ---------------------------------------------------------------------------
// fp32 causal row softmax -> bf16 hi/lo P
// ---------------------------------------------------------------------------
__global__ __launch_bounds__(256) void softmax_kernel()
{
    const int m = blockIdx.x, b = blockIdx.y;
    const size_t roff = (size_t)b * SEQ * SEQ + (size_t)m * SEQ;
    const float* row = g_p + roff;
    const int nv = m + 1;
    const int tid = threadIdx.x;
    __shared__ float red[8];

    float mx = -3.4e38f;
    for (int n = tid; n < nv; n += 256) mx = fmaxf(mx, row[n]);
    #pragma unroll
    for (int o = 16; o; o >>= 1) mx = fmaxf(mx, __shfl_xor_sync(0xffffffffu, mx, o));
    if ((tid & 31) == 0) red[tid >> 5] = mx;
    __syncthreads();
    float mall = red[0];
    #pragma unroll
    for (int i = 1; i < 8; i++) mall = fmaxf(mall, red[i]);
    __syncthreads();

    float s = 0.f;
    for (int n = tid; n < nv; n += 256) s += __expf(row[n] - mall);
    #pragma unroll
    for (int o = 16; o; o >>= 1) s += __shfl_xor_sync(0xffffffffu, s, o);
    if ((tid & 31) == 0) red[tid >> 5] = s;
    __syncthreads();
    float tot = 0.f;
    #pragma unroll
    for (int i = 0; i < 8; i++) tot += red[i];
    const float inv = 1.0f / tot;

    bf16* ph = g_ph + roff;
    bf16* pl = g_pl + roff;
    for (int n2 = tid; n2 < SEQ / 2; n2 += 256) {
        const int n = n2 * 2;
        float p0 = (n     < nv) ? __expf(row[n]     - mall) * inv : 0.f;
        float p1 = (n + 1 < nv) ? __expf(row[n + 1] - mall) * inv : 0.f;
        uint32_t h, l;
        split2(p0, p1, h, l);
        *(uint32_t*)(ph + n) = h;
        *(uint32_t*)(pl + n) = l;
    }
}

// ---------------------------------------------------------------------------
extern "C" void kernel_launch(void* const* d_in, const int* in_sizes, int n_in,
                              void* d_out, int out_size)
{
    const float* xs   = (const float*)d_in[0];
    const float* WQ_w = (const float*)d_in[1];
    const float* WQ_b = (const float*)d_in[2];
    const float* WK_w = (const float*)d_in[3];
    const float* WK_b = (const float*)d_in[4];
    const float* WV_w = (const float*)d_in[5];
    const float* WV_b = (const float*)d_in[6];
    float* out = (float*)d_out;

    cudaFuncSetAttribute(proj_qk_kernel, cudaFuncAttributeMaxDynamicSharedMemorySize, SMEM_BYTES);
    cudaFuncSetAttribute(proj_vt_kernel, cudaFuncAttributeMaxDynamicSharedMemorySize, SMEM_BYTES);
    cudaFuncSetAttribute(qkt_kernel,     cudaFuncAttributeMaxDynamicSharedMemorySize, SMEM_BYTES);
    cudaFuncSetAttribute(pv_kernel,      cudaFuncAttributeMaxDynamicSharedMemorySize, SMEM_BYTES);

    prep_kernel<<<dim3(512, 4), 256>>>(xs, WQ_w, WK_w, WV_w);
    proj_qk_kernel<<<dim3(EDIM / 128, MTOT / 128, 2), NTHREADS, SMEM_BYTES>>>(WQ_b, WK_b);
    proj_vt_kernel<<<dim3(MTOT / 128, EDIM / 128, 1), NTHREADS, SMEM_BYTES>>>(WV_b);
    qkt_kernel<<<dim3(SEQ / 128, SEQ / 128, BATCH), NTHREADS, SMEM_BYTES>>>();
    softmax_kernel<<<dim3(SEQ, BATCH), 256>>>();
    pv_kernel<<<dim3(EDIM / 128, SEQ / 128, BATCH), NTHREADS, SMEM_BYTES>>>(out);
}

// round 16
// speedup vs baseline: 1.1799x; 1.1799x over previous
#include <cuda_runtime.h>
#include <cuda_bf16.h>
#include <stdint.h>
#include <math.h>

#define BATCH 4
#define SEQ   2048
#define HDIM  1024
#define EDIM  1024
#define MTOT  (BATCH * SEQ)          // 8192

typedef __nv_bfloat16 bf16;

// ---------------------------------------------------------------------------
// Scratch (device globals)
// ---------------------------------------------------------------------------
__device__ bf16  g_xh[(size_t)MTOT * HDIM],  g_xl[(size_t)MTOT * HDIM];
__device__ bf16  g_wh[(size_t)3 * EDIM * HDIM], g_wl[(size_t)3 * EDIM * HDIM];
__device__ bf16  g_qh[(size_t)MTOT * EDIM],  g_ql[(size_t)MTOT * EDIM];
__device__ bf16  g_kh[(size_t)MTOT * EDIM],  g_kl[(size_t)MTOT * EDIM];
__device__ bf16  g_vth[(size_t)EDIM * MTOT], g_vtl[(size_t)EDIM * MTOT];
__device__ float g_p [(size_t)BATCH * SEQ * SEQ];
__device__ bf16  g_ph[(size_t)BATCH * SEQ * SEQ], g_pl[(size_t)BATCH * SEQ * SEQ];

// ---------------------------------------------------------------------------
// Geometry (R9 best): CTA 128x128, K-chunk = 64 bf16 = 128B rows, XOR swizzle
// seg' = seg ^ (row & 7). 512 threads = 16 warps (4x4), warp tile 32x32.
// ---------------------------------------------------------------------------
#define TILE_B   (128 * 128)           // 16384 B per 128x64 bf16 tile
#define STAGE_B  (4 * TILE_B)          // Ah, Al, Bh, Bl = 65536 B
#define SMEM_BYTES (2 * STAGE_B)       // 131072 B double buffered
#define NTHREADS 512

// qkt tile enumeration: lower triangle of 16x16 tile grid per batch
#define QKT_TILES_PER_B 136            // 16*17/2
#define QKT_TILES (BATCH * QKT_TILES_PER_B)   // 544
#define VT_TILES  ((MTOT / 128) * (EDIM / 128))  // 64 * 8 = 512
#define MID_TILES (QKT_TILES + VT_TILES)         // 1056

__device__ __forceinline__ uint32_t smem_u32(const void* p) {
    uint32_t a;
    asm("{ .reg .u64 t; cvta.to.shared.u64 t, %1; cvt.u32.u64 %0, t; }"
        : "=r"(a) : "l"(p));
    return a;
}
__device__ __forceinline__ void cp_async16(uint32_t dst, const void* src) {
    asm volatile("cp.async.cg.shared.global [%0], [%1], 16;"
                 :: "r"(dst), "l"(src));
}
__device__ __forceinline__ void cp_commit() {
    asm volatile("cp.async.commit_group;" ::: "memory");
}
template<int N> __device__ __forceinline__ void cp_wait() {
    asm volatile("cp.async.wait_group %0;" :: "n"(N) : "memory");
}
__device__ __forceinline__ void ldsm4(uint32_t* r, uint32_t addr) {
    asm volatile("ldmatrix.sync.aligned.m8n8.x4.shared.b16 {%0,%1,%2,%3}, [%4];"
                 : "=r"(r[0]), "=r"(r[1]), "=r"(r[2]), "=r"(r[3]) : "r"(addr));
}
__device__ __forceinline__ void mma16816(float* c, const uint32_t* a,
                                         uint32_t b0, uint32_t b1) {
    asm volatile(
        "mma.sync.aligned.m16n8k16.row.col.f32.bf16.bf16.f32 "
        "{%0,%1,%2,%3}, {%4,%5,%6,%7}, {%8,%9}, {%0,%1,%2,%3};"
        : "+f"(c[0]), "+f"(c[1]), "+f"(c[2]), "+f"(c[3])
        : "r"(a[0]), "r"(a[1]), "r"(a[2]), "r"(a[3]), "r"(b0), "r"(b1));
}
__device__ __forceinline__ void split2(float x, float y, uint32_t& h, uint32_t& l) {
    __nv_bfloat162 hh = __floats2bfloat162_rn(x, y);
    float rx = x - __low2float(hh);
    float ry = y - __high2float(hh);
    __nv_bfloat162 ll = __floats2bfloat162_rn(rx, ry);
    h = *(uint32_t*)&hh; l = *(uint32_t*)&ll;
}

// ---------------------------------------------------------------------------
// Issue one K-chunk (4 tiles of 128 rows x 128B) via cp.async, swizzled.
// 512 threads x 2 segs per tile x 4 tiles = 8 cp.async16 per thread.
// ---------------------------------------------------------------------------
__device__ __forceinline__ void stage_issue(
    const bf16* __restrict__ Ah, const bf16* __restrict__ Al, size_t lda,
    const bf16* __restrict__ Bh, const bf16* __restrict__ Bl, size_t ldb,
    int m0, int n0, int kt, uint32_t st, int tid)
{
    #pragma unroll
    for (int t = 0; t < 4; t++) {
        const bf16* base = (t == 0) ? Ah : (t == 1) ? Al : (t == 2) ? Bh : Bl;
        const size_t ld  = (t < 2) ? lda : ldb;
        const int    r0  = (t < 2) ? m0 : n0;
        #pragma unroll
        for (int jj = 0; jj < 2; jj++) {
            int idx = tid * 2 + jj;          // 0..1023
            int r   = idx >> 3;              // 0..127
            int j   = idx & 7;               // 16B segment 0..7
            const bf16* gp = base + (size_t)(r0 + r) * ld + kt + j * 8;
            uint32_t dst = st + t * TILE_B + r * 128 + ((j ^ (r & 7)) << 4);
            cp_async16(dst, gp);
        }
    }
}

// ---------------------------------------------------------------------------
// 128x128 GEMM: C[m,n] = scale * sum_k A[m,k]*B[n,k] (+bias), bf16 split.
// cp.async 2-stage ring (K-chunk 64), one barrier per chunk, swizzled smem.
// ---------------------------------------------------------------------------
__device__ void gemm_mma(
    const bf16* __restrict__ Ah, const bf16* __restrict__ Al, size_t lda,
    const bf16* __restrict__ Bh, const bf16* __restrict__ Bl, size_t ldb,
    float* __restrict__ C, bf16* __restrict__ Ch, bf16* __restrict__ Cl,
    size_t ldc, const float* __restrict__ bias, int bias_mode, float scale,
    int m0, int n0, int nchunks)
{
    extern __shared__ __align__(128) char smem[];
    const uint32_t sbase = smem_u32(smem);
    const int tid  = threadIdx.x;
    const int lane = tid & 31;
    const int wid  = tid >> 5;       // 0..15
    const int wm   = wid >> 2;       // 0..3  (32-row slice)
    const int wn   = wid & 3;        // 0..3  (32-col slice)

    float acc[2][4][4];
    #pragma unroll
    for (int i = 0; i < 2; i++)
        #pragma unroll
        for (int j = 0; j < 4; j++)
            #pragma unroll
            for (int q = 0; q < 4; q++) acc[i][j][q] = 0.f;

    const uint32_t a_row = (uint32_t)((wm * 32 + (lane & 15)) * 128);
    const uint32_t b_row = (uint32_t)((wn * 32 + (lane & 7) + ((lane >> 4) << 3)) * 128);
    const uint32_t lx    = (uint32_t)(lane & 7);          // swizzle key
    const uint32_t a_sg  = (uint32_t)(lane >> 4);         // 0/1
    const uint32_t b_sg  = (uint32_t)((lane >> 3) & 1);   // 0/1

    // prologue: chunk 0 -> buffer 0
    stage_issue(Ah, Al, lda, Bh, Bl, ldb, m0, n0, 0, sbase, tid);
    cp_commit();

    for (int c = 0; c < nchunks; ++c) {
        cp_wait<0>();
        __syncthreads();                 // chunk c visible; WAR for other buffer

        if (c + 1 < nchunks) {
            stage_issue(Ah, Al, lda, Bh, Bl, ldb, m0, n0, (c + 1) * 64,
                        sbase + ((c + 1) & 1) * STAGE_B, tid);
            cp_commit();
        }

        const uint32_t hiA = sbase + (c & 1) * STAGE_B;
        const uint32_t loA = hiA + TILE_B;
        const uint32_t hiB = hiA + 2 * TILE_B;
        const uint32_t loB = hiA + 3 * TILE_B;

        #pragma unroll
        for (int s = 0; s < 4; s++) {    // 4 k16-steps per 64-wide chunk
            const uint32_t aw = (((uint32_t)(2 * s) + a_sg) ^ lx) << 4;
            const uint32_t bw = (((uint32_t)(2 * s) + b_sg) ^ lx) << 4;
            uint32_t ah[2][4], al[2][4], bh[2][4], bl[2][4];
            #pragma unroll
            for (int mt = 0; mt < 2; mt++)
                ldsm4(ah[mt], hiA + a_row + mt * 16 * 128 + aw);
            #pragma unroll
            for (int mt = 0; mt < 2; mt++)
                ldsm4(al[mt], loA + a_row + mt * 16 * 128 + aw);
            #pragma unroll
            for (int p = 0; p < 2; p++)
                ldsm4(bh[p], hiB + b_row + p * 16 * 128 + bw);
            #pragma unroll
            for (int p = 0; p < 2; p++)
                ldsm4(bl[p], loB + b_row + p * 16 * 128 + bw);

            #pragma unroll
            for (int mt = 0; mt < 2; mt++)
                #pragma unroll
                for (int p = 0; p < 2; p++) {
                    mma16816(acc[mt][2 * p],     ah[mt], bh[p][0], bh[p][1]);
                    mma16816(acc[mt][2 * p + 1], ah[mt], bh[p][2], bh[p][3]);
                }
            #pragma unroll
            for (int mt = 0; mt < 2; mt++)
                #pragma unroll
                for (int p = 0; p < 2; p++) {
                    mma16816(acc[mt][2 * p],     al[mt], bh[p][0], bh[p][1]);
                    mma16816(acc[mt][2 * p + 1], al[mt], bh[p][2], bh[p][3]);
                }
            #pragma unroll
            for (int mt = 0; mt < 2; mt++)
                #pragma unroll
                for (int p = 0; p < 2; p++) {
                    mma16816(acc[mt][2 * p],     ah[mt], bl[p][0], bl[p][1]);
                    mma16816(acc[mt][2 * p + 1], ah[mt], bl[p][2], bl[p][3]);
                }
        }
        // no bottom barrier: next write to this buffer only after the top
        // barrier of chunk c+1.
    }

    // epilogue: warp tile 32x32
    const int g   = lane >> 2;
    const int tig = lane & 3;
    #pragma unroll
    for (int mt = 0; mt < 2; mt++) {
        const int r0 = m0 + wm * 32 + mt * 16 + g;
        #pragma unroll
        for (int nt = 0; nt < 4; nt++) {
            const int col = n0 + wn * 32 + nt * 8 + tig * 2;
            float b0 = 0.f, b1 = 0.f;
            if (bias_mode == 1) { b0 = bias[col]; b1 = bias[col + 1]; }
            float v00 = acc[mt][nt][0] * scale + b0;
            float v01 = acc[mt][nt][1] * scale + b1;
            float v10 = acc[mt][nt][2] * scale + b0;
            float v11 = acc[mt][nt][3] * scale + b1;
            if (bias_mode == 2) {
                float rb0 = bias[r0], rb1 = bias[r0 + 8];
                v00 += rb0; v01 += rb0; v10 += rb1; v11 += rb1;
            }
            if (C) {
                *(float2*)(C + (size_t)r0 * ldc + col)       = make_float2(v00, v01);
                *(float2*)(C + (size_t)(r0 + 8) * ldc + col) = make_float2(v10, v11);
            } else {
                uint32_t h0, l0, h1, l1;
                split2(v00, v01, h0, l0);
                split2(v10, v11, h1, l1);
                *(uint32_t*)(Ch + (size_t)r0 * ldc + col)       = h0;
                *(uint32_t*)(Cl + (size_t)r0 * ldc + col)       = l0;
                *(uint32_t*)(Ch + (size_t)(r0 + 8) * ldc + col) = h1;
                *(uint32_t*)(Cl + (size_t)(r0 + 8) * ldc + col) = l1;
            }
        }
    }
}

// ---------------------------------------------------------------------------
// Prep: split xs and the 3 weight matrices into bf16 hi/lo.
// ---------------------------------------------------------------------------
__device__ __forceinline__ void cvt_arr(const float* __restrict__ in,
                                        bf16* __restrict__ hi,
                                        bf16* __restrict__ lo, size_t n4)
{
    const size_t t0 = blockIdx.x * blockDim.x + threadIdx.x;
    const size_t stride = (size_t)gridDim.x * blockDim.x;
    for (size_t i = t0; i < n4; i += stride) {
        float4 v = ((const float4*)in)[i];
        uint32_t h0, l0, h1, l1;
        split2(v.x, v.y, h0, l0);
        split2(v.z, v.w, h1, l1);
        ((uint2*)hi)[i] = make_uint2(h0, h1);
        ((uint2*)lo)[i] = make_uint2(l0, l1);
    }
}

__global__ __launch_bounds__(256) void prep_kernel(
    const float* __restrict__ xs, const float* __restrict__ wq,
    const float* __restrict__ wk, const float* __restrict__ wv)
{
    const size_t WN = (size_t)EDIM * HDIM;
    if      (blockIdx.y == 0) cvt_arr(xs, g_xh, g_xl, (size_t)MTOT * HDIM / 4);
    else if (blockIdx.y == 1) cvt_arr(wq, g_wh,          g_wl,          WN / 4);
    else if (blockIdx.y == 2) cvt_arr(wk, g_wh + WN,     g_wl + WN,     WN / 4);
    else                      cvt_arr(wv, g_wh + 2 * WN, g_wl + 2 * WN, WN / 4);
}

// ---------------------------------------------------------------------------
// Kernel A: Q/K projections. grid (E/128, M/128, 2)
// ---------------------------------------------------------------------------
__global__ __launch_bounds__(NTHREADS, 1)
void proj_qk_kernel(const float* __restrict__ bq, const float* __restrict__ bk)
{
    const size_t WN = (size_t)EDIM * HDIM;
    const int z = blockIdx.z;
    gemm_mma(g_xh, g_xl, HDIM,
             g_wh + z * WN, g_wl + z * WN, HDIM,
             nullptr, z ? g_kh : g_qh, z ? g_kl : g_ql, EDIM,
             z ? bk : bq, 1, 1.0f,
             blockIdx.y * 128, blockIdx.x * 128, HDIM / 64);
}

// ---------------------------------------------------------------------------
// Kernel B (merged): causal QK^T tiles (lower triangle only) + V^T projection
// tiles, one linearized grid of 1056 CTAs -> single wave tail.
// ---------------------------------------------------------------------------
__global__ __launch_bounds__(NTHREADS, 1)
void mid_kernel(const float* __restrict__ bv)
{
    const int t = blockIdx.x;
    const bf16 *Ah, *Al, *Bh, *Bl;
    size_t lda, ldb, ldc;
    float* C; bf16 *Ch, *Cl;
    const float* bias; int bias_mode; float scale;
    int m0, n0;

    if (t < QKT_TILES) {
        const int b = t / QKT_TILES_PER_B;
        const int r = t % QKT_TILES_PER_B;
        // decode lower-triangle index: r = y*(y+1)/2 + x, x <= y
        int y = (int)((sqrtf(8.0f * (float)r + 1.0f) - 1.0f) * 0.5f);
        while ((y + 1) * (y + 2) / 2 <= r) y++;
        while (y * (y + 1) / 2 > r) y--;
        const int x = r - y * (y + 1) / 2;
        Ah = g_qh + (size_t)b * SEQ * EDIM; Al = g_ql + (size_t)b * SEQ * EDIM;
        Bh = g_kh + (size_t)b * SEQ * EDIM; Bl = g_kl + (size_t)b * SEQ * EDIM;
        lda = EDIM; ldb = EDIM; ldc = SEQ;
        C = g_p + (size_t)b * SEQ * SEQ; Ch = nullptr; Cl = nullptr;
        bias = nullptr; bias_mode = 0; scale = 0.03125f;
        m0 = y * 128; n0 = x * 128;
        gemm_mma(Ah, Al, lda, Bh, Bl, ldb, C, Ch, Cl, ldc,
                 bias, bias_mode, scale, m0, n0, EDIM / 64);
    } else {
        const int r = t - QKT_TILES;     // 0..511
        const int y = r >> 6;            // 0..7  (EDIM tile)
        const int x = r & 63;            // 0..63 (MTOT tile)
        const size_t WN = (size_t)EDIM * HDIM;
        gemm_mma(g_wh + 2 * WN, g_wl + 2 * WN, HDIM,
                 g_xh, g_xl, HDIM,
                 nullptr, g_vth, g_vtl, MTOT,
                 bv, 2, 1.0f,
                 y * 128, x * 128, HDIM / 64);
    }
}

// ---------------------------------------------------------------------------
// Kernel D: y = P @ V^T. Heavy tiles (large K bound) launch first.
// ---------------------------------------------------------------------------
__global__ __launch_bounds__(NTHREADS, 1)
void pv_kernel(float* __restrict__ out)
{
    const int b = blockIdx.z;
    const int y = (int)gridDim.y - 1 - (int)blockIdx.y;   // heavy-first
    const int nchunks = (y + 1) * 2;    // K bound = (y+1)*128, chunk 64
    gemm_mma(g_ph + (size_t)b * SEQ * SEQ, g_pl + (size_t)b * SEQ * SEQ, SEQ,
             g_vth + (size_t)b * SEQ, g_vtl + (size_t)b * SEQ, MTOT,
             out + (size_t)b * SEQ * EDIM, nullptr, nullptr, EDIM,
             nullptr, 0, 1.0f,
             y * 128, blockIdx.x * 128, nchunks);
}

// ---------------------------------------------------------------------------
// fp32 causal row softmax -> bf16 hi/lo P
// ---------------------------------------------------------------------------
__global__ __launch_bounds__(256) void softmax_kernel()
{
    const int m = blockIdx.x, b = blockIdx.y;
    const size_t roff = (size_t)b * SEQ * SEQ + (size_t)m * SEQ;
    const float* row = g_p + roff;
    const int nv = m + 1;
    const int tid = threadIdx.x;
    __shared__ float red[8];

    float mx = -3.4e38f;
    for (int n = tid; n < nv; n += 256) mx = fmaxf(mx, row[n]);
    #pragma unroll
    for (int o = 16; o; o >>= 1) mx = fmaxf(mx, __shfl_xor_sync(0xffffffffu, mx, o));
    if ((tid & 31) == 0) red[tid >> 5] = mx;
    __syncthreads();
    float mall = red[0];
    #pragma unroll
    for (int i = 1; i < 8; i++) mall = fmaxf(mall, red[i]);
    __syncthreads();

    float s = 0.f;
    for (int n = tid; n < nv; n += 256) s += __expf(row[n] - mall);
    #pragma unroll
    for (int o = 16; o; o >>= 1) s += __shfl_xor_sync(0xffffffffu, s, o);
    if ((tid & 31) == 0) red[tid >> 5] = s;
    __syncthreads();
    float tot = 0.f;
    #pragma unroll
    for (int i = 0; i < 8; i++) tot += red[i];
    const float inv = 1.0f / tot;

    bf16* ph = g_ph + roff;
    bf16* pl = g_pl + roff;
    for (int n2 = tid; n2 < SEQ / 2; n2 += 256) {
        const int n = n2 * 2;
        float p0 = (n     < nv) ? __expf(row[n]     - mall) * inv : 0.f;
        float p1 = (n + 1 < nv) ? __expf(row[n + 1] - mall) * inv : 0.f;
        uint32_t h, l;
        split2(p0, p1, h, l);
        *(uint32_t*)(ph + n) = h;
        *(uint32_t*)(pl + n) = l;
    }
}

// ---------------------------------------------------------------------------
extern "C" void kernel_launch(void* const* d_in, const int* in_sizes, int n_in,
                              void* d_out, int out_size)
{
    const float* xs   = (const float*)d_in[0];
    const float* WQ_w = (const float*)d_in[1];
    const float* WQ_b = (const float*)d_in[2];
    const float* WK_w = (const float*)d_in[3];
    const float* WK_b = (const float*)d_in[4];
    const float* WV_w = (const float*)d_in[5];
    const float* WV_b = (const float*)d_in[6];
    float* out = (float*)d_out;

    cudaFuncSetAttribute(proj_qk_kernel, cudaFuncAttributeMaxDynamicSharedMemorySize, SMEM_BYTES);
    cudaFuncSetAttribute(mid_kernel,     cudaFuncAttributeMaxDynamicSharedMemorySize, SMEM_BYTES);
    cudaFuncSetAttribute(pv_kernel,      cudaFuncAttributeMaxDynamicSharedMemorySize, SMEM_BYTES);

    prep_kernel<<<dim3(512, 4), 256>>>(xs, WQ_w, WK_w, WV_w);
    proj_qk_kernel<<<dim3(EDIM / 128, MTOT / 128, 2), NTHREADS, SMEM_BYTES>>>(WQ_b, WK_b);
    mid_kernel<<<dim3(MID_TILES), NTHREADS, SMEM_BYTES>>>(WV_b);
    softmax_kernel<<<dim3(SEQ, BATCH), 256>>>();
    pv_kernel<<<dim3(EDIM / 128, SEQ / 128, BATCH), NTHREADS, SMEM_BYTES>>>(out);
}